// round 2
// baseline (speedup 1.0000x reference)
#include <cuda_runtime.h>

#define NN_MAX 100000
#define EE_MAX 1600000
#define D 64
#define EPSV 1e-12f

// Scratch (no allocations allowed)
__device__ float g_e[EE_MAX];      // per-edge exp(logit)
__device__ float g_denom[NN_MAX];  // segment sum of exp over dst
__device__ float g_invn[NN_MAX];   // 1/max(||feat_row||, eps)

// ---------------------------------------------------------------------------
// K0: zero output (harness poisons it) + per-node denom
__global__ void k_init(float* __restrict__ out, int n_nodes) {
    int i = blockIdx.x * blockDim.x + threadIdx.x;
    if (i < n_nodes * D) out[i] = 0.0f;
    if (i < n_nodes) g_denom[i] = 0.0f;
}

// ---------------------------------------------------------------------------
// K1: per-row inverse L2 norm (warp per row, float2 lanes)
__global__ void k_norm(const float* __restrict__ feat, int n_nodes) {
    int w    = (blockIdx.x * blockDim.x + threadIdx.x) >> 5;
    int lane = threadIdx.x & 31;
    if (w >= n_nodes) return;
    float2 v = reinterpret_cast<const float2*>(feat + (size_t)w * D)[lane];
    float s = v.x * v.x + v.y * v.y;
    #pragma unroll
    for (int o = 16; o; o >>= 1) s += __shfl_xor_sync(0xffffffffu, s, o);
    if (lane == 0) g_invn[w] = 1.0f / fmaxf(sqrtf(s), EPSV);
}

// ---------------------------------------------------------------------------
// K2: per-edge cosine -> exp -> denom accumulation (warp per edge)
// logits bounded by |beta| (cos in [-1,1], beta==1): safe without max-shift,
// and softmax is shift-invariant, so result matches the reference.
__global__ void k_dotexp(const float* __restrict__ feat,
                         const float* __restrict__ beta,
                         const int* __restrict__ src,
                         const int* __restrict__ dst,
                         int n_edges) {
    int w    = (blockIdx.x * blockDim.x + threadIdx.x) >> 5;
    int lane = threadIdx.x & 31;
    if (w >= n_edges) return;
    int s = src[w];
    int d = dst[w];
    float2 a = reinterpret_cast<const float2*>(feat + (size_t)s * D)[lane];
    float2 b = reinterpret_cast<const float2*>(feat + (size_t)d * D)[lane];
    float p = a.x * b.x + a.y * b.y;
    #pragma unroll
    for (int o = 16; o; o >>= 1) p += __shfl_xor_sync(0xffffffffu, p, o);
    if (lane == 0) {
        float e  = beta[0] * g_invn[s] * g_invn[d] * p;  // TEMP == 1
        float ex = __expf(e);
        g_e[w] = ex;
        atomicAdd(&g_denom[d], ex);
    }
}

// ---------------------------------------------------------------------------
// K3: gather-scale-scatter aggregation (warp per edge, atomic scatter)
__global__ void k_agg(const float* __restrict__ feat,
                      const int* __restrict__ src,
                      const int* __restrict__ dst,
                      float* __restrict__ out, int n_edges) {
    int w    = (blockIdx.x * blockDim.x + threadIdx.x) >> 5;
    int lane = threadIdx.x & 31;
    if (w >= n_edges) return;
    int s = src[w];
    int d = dst[w];
    float attn = g_e[w] / fmaxf(g_denom[d], EPSV);
    float2 a = reinterpret_cast<const float2*>(feat + (size_t)s * D)[lane];
    float* od = out + (size_t)d * D + lane * 2;
    atomicAdd(od,     a.x * attn);
    atomicAdd(od + 1, a.y * attn);
}

// ---------------------------------------------------------------------------
extern "C" void kernel_launch(void* const* d_in, const int* in_sizes, int n_in,
                              void* d_out, int out_size) {
    const float* feat = (const float*)d_in[0];
    const float* beta = (const float*)d_in[1];
    const int*   src  = (const int*)d_in[2];   // JAX silently int32 (no x64)
    const int*   dst  = (const int*)d_in[3];
    float*       out  = (float*)d_out;

    int n_nodes = in_sizes[0] / D;
    int n_edges = in_sizes[2];
    if (n_nodes > NN_MAX) n_nodes = NN_MAX;
    if (n_edges > EE_MAX) n_edges = EE_MAX;

    const int T = 256;  // 8 warps/block
    int init_blocks  = (n_nodes * D + T - 1) / T;
    int row_blocks   = (n_nodes + 7) / 8;
    int edgew_blocks = (n_edges + 7) / 8;

    k_init   <<<init_blocks, T>>>(out, n_nodes);
    k_norm   <<<row_blocks, T>>>(feat, n_nodes);
    k_dotexp <<<edgew_blocks, T>>>(feat, beta, src, dst, n_edges);
    k_agg    <<<edgew_blocks, T>>>(feat, src, dst, out, n_edges);
}

// round 3
// speedup vs baseline: 1.0043x; 1.0043x over previous
#include <cuda_runtime.h>

#define NN_MAX 100000
#define EE_MAX 1600000
#define D 64
#define EPSV 1e-12f

// Scratch (no allocations allowed)
__device__ float g_e[EE_MAX];      // per-edge exp(logit)
__device__ float g_denom[NN_MAX];  // segment sum of exp over dst
__device__ float g_invn[NN_MAX];   // 1/max(||feat_row||, eps)

// ---------------------------------------------------------------------------
// K0: zero output (harness poisons it) + per-node denom
__global__ void k_init(float* __restrict__ out, int n_nodes) {
    int i = blockIdx.x * blockDim.x + threadIdx.x;
    if (i < n_nodes * D) out[i] = 0.0f;
    if (i < n_nodes) g_denom[i] = 0.0f;
}

// ---------------------------------------------------------------------------
// K1: per-row inverse L2 norm (warp per row, float2 lanes)
__global__ void k_norm(const float* __restrict__ feat, int n_nodes) {
    int w    = (blockIdx.x * blockDim.x + threadIdx.x) >> 5;
    int lane = threadIdx.x & 31;
    if (w >= n_nodes) return;
    float2 v = reinterpret_cast<const float2*>(feat + (size_t)w * D)[lane];
    float s = v.x * v.x + v.y * v.y;
    #pragma unroll
    for (int o = 16; o; o >>= 1) s += __shfl_xor_sync(0xffffffffu, s, o);
    if (lane == 0) g_invn[w] = 1.0f / fmaxf(sqrtf(s), EPSV);
}

// ---------------------------------------------------------------------------
// K2: per-edge cosine -> exp -> denom accumulation (warp per edge)
// logits bounded by |beta| (cos in [-1,1], beta==1): safe without max-shift,
// and softmax is shift-invariant, so result matches the reference.
__global__ void k_dotexp(const float* __restrict__ feat,
                         const float* __restrict__ beta,
                         const int* __restrict__ src,
                         const int* __restrict__ dst,
                         int n_edges) {
    int w    = (blockIdx.x * blockDim.x + threadIdx.x) >> 5;
    int lane = threadIdx.x & 31;
    if (w >= n_edges) return;
    int s = src[w];
    int d = dst[w];
    float2 a = reinterpret_cast<const float2*>(feat + (size_t)s * D)[lane];
    float2 b = reinterpret_cast<const float2*>(feat + (size_t)d * D)[lane];
    float p = a.x * b.x + a.y * b.y;
    #pragma unroll
    for (int o = 16; o; o >>= 1) p += __shfl_xor_sync(0xffffffffu, p, o);
    if (lane == 0) {
        float e  = beta[0] * g_invn[s] * g_invn[d] * p;  // TEMP == 1
        float ex = __expf(e);
        g_e[w] = ex;
        atomicAdd(&g_denom[d], ex);
    }
}

// ---------------------------------------------------------------------------
// K3: gather-scale-scatter aggregation (warp per edge, atomic scatter)
__global__ void k_agg(const float* __restrict__ feat,
                      const int* __restrict__ src,
                      const int* __restrict__ dst,
                      float* __restrict__ out, int n_edges) {
    int w    = (blockIdx.x * blockDim.x + threadIdx.x) >> 5;
    int lane = threadIdx.x & 31;
    if (w >= n_edges) return;
    int s = src[w];
    int d = dst[w];
    float attn = g_e[w] / fmaxf(g_denom[d], EPSV);
    float2 a = reinterpret_cast<const float2*>(feat + (size_t)s * D)[lane];
    float* od = out + (size_t)d * D + lane * 2;
    atomicAdd(od,     a.x * attn);
    atomicAdd(od + 1, a.y * attn);
}

// ---------------------------------------------------------------------------
extern "C" void kernel_launch(void* const* d_in, const int* in_sizes, int n_in,
                              void* d_out, int out_size) {
    const float* feat = (const float*)d_in[0];
    const float* beta = (const float*)d_in[1];
    const int*   src  = (const int*)d_in[2];   // JAX silently int32 (no x64)
    const int*   dst  = (const int*)d_in[3];
    float*       out  = (float*)d_out;

    int n_nodes = in_sizes[0] / D;
    int n_edges = in_sizes[2];
    if (n_nodes > NN_MAX) n_nodes = NN_MAX;
    if (n_edges > EE_MAX) n_edges = EE_MAX;

    const int T = 256;  // 8 warps/block
    int init_blocks  = (n_nodes * D + T - 1) / T;
    int row_blocks   = (n_nodes + 7) / 8;
    int edgew_blocks = (n_edges + 7) / 8;

    k_init   <<<init_blocks, T>>>(out, n_nodes);
    k_norm   <<<row_blocks, T>>>(feat, n_nodes);
    k_dotexp <<<edgew_blocks, T>>>(feat, beta, src, dst, n_edges);
    k_agg    <<<edgew_blocks, T>>>(feat, src, dst, out, n_edges);
}

// round 4
// speedup vs baseline: 1.7354x; 1.7280x over previous
#include <cuda_runtime.h>

#define NN_MAX 100000
#define EE_MAX 1600000
#define D 64
#define EPSV 1e-12f
#define SCAN_B 1024

// Scratch (no allocations allowed)
__device__ float g_invn[NN_MAX];        // 1/max(||feat_row||, eps)
__device__ int   g_hist[NN_MAX];        // in-degree
__device__ int   g_rowptr[NN_MAX + 1];  // CSR row pointers (by dst)
__device__ int   g_cursor[NN_MAX];      // scatter cursors
__device__ int   g_bsums[SCAN_B];       // scan block sums
__device__ int   g_esrc[EE_MAX];        // src ids grouped by dst

// ---------------------------------------------------------------------------
__global__ void k_zero(int n_nodes) {
    int i = blockIdx.x * blockDim.x + threadIdx.x;
    if (i < n_nodes) g_hist[i] = 0;
}

// per-row inverse L2 norm (warp per row)
__global__ void k_norm(const float* __restrict__ feat, int n_nodes) {
    int w    = (blockIdx.x * blockDim.x + threadIdx.x) >> 5;
    int lane = threadIdx.x & 31;
    if (w >= n_nodes) return;
    float2 v = reinterpret_cast<const float2*>(feat + (size_t)w * D)[lane];
    float s = v.x * v.x + v.y * v.y;
    #pragma unroll
    for (int o = 16; o; o >>= 1) s += __shfl_xor_sync(0xffffffffu, s, o);
    if (lane == 0) g_invn[w] = 1.0f / fmaxf(sqrtf(s), EPSV);
}

// in-degree histogram
__global__ void k_hist(const int* __restrict__ dst, int n_edges) {
    int i = blockIdx.x * blockDim.x + threadIdx.x;
    if (i < n_edges) atomicAdd(&g_hist[dst[i]], 1);
}

// exclusive scan, stage 1: per-block scan + block totals
__global__ void k_scan1(int n_nodes) {
    __shared__ int sh[SCAN_B];
    int i = blockIdx.x * SCAN_B + threadIdx.x;
    int v = (i < n_nodes) ? g_hist[i] : 0;
    sh[threadIdx.x] = v;
    __syncthreads();
    for (int o = 1; o < SCAN_B; o <<= 1) {
        int t = (threadIdx.x >= o) ? sh[threadIdx.x - o] : 0;
        __syncthreads();
        sh[threadIdx.x] += t;
        __syncthreads();
    }
    if (i < n_nodes) g_rowptr[i] = sh[threadIdx.x] - v;     // exclusive (partial)
    if (threadIdx.x == SCAN_B - 1) g_bsums[blockIdx.x] = sh[SCAN_B - 1];
}

// stage 2: single-block exclusive scan of block sums
__global__ void k_scan2(int n_blocks) {
    __shared__ int sh[SCAN_B];
    int v = (threadIdx.x < n_blocks) ? g_bsums[threadIdx.x] : 0;
    sh[threadIdx.x] = v;
    __syncthreads();
    for (int o = 1; o < SCAN_B; o <<= 1) {
        int t = (threadIdx.x >= o) ? sh[threadIdx.x - o] : 0;
        __syncthreads();
        sh[threadIdx.x] += t;
        __syncthreads();
    }
    if (threadIdx.x < n_blocks) g_bsums[threadIdx.x] = sh[threadIdx.x] - v;
}

// stage 3: add block offsets, init cursors, cap row_ptr
__global__ void k_scan3(int n_nodes, int n_edges) {
    int i = blockIdx.x * SCAN_B + threadIdx.x;
    if (i < n_nodes) {
        int r = g_rowptr[i] + g_bsums[blockIdx.x];
        g_rowptr[i] = r;
        g_cursor[i] = r;
    }
    if (i == 0) g_rowptr[n_nodes] = n_edges;
}

// bucket src ids by dst
__global__ void k_scatter(const int* __restrict__ src,
                          const int* __restrict__ dst, int n_edges) {
    int i = blockIdx.x * blockDim.x + threadIdx.x;
    if (i >= n_edges) return;
    int pos = atomicAdd(&g_cursor[dst[i]], 1);
    g_esrc[pos] = src[i];
}

// ---------------------------------------------------------------------------
// fused: per-dst softmax + aggregation, atomic-free (warp per dst)
__global__ void k_agg(const float* __restrict__ feat,
                      const float* __restrict__ beta,
                      float* __restrict__ out, int n_nodes) {
    int w    = (blockIdx.x * blockDim.x + threadIdx.x) >> 5;
    int lane = threadIdx.x & 31;
    if (w >= n_nodes) return;

    float2 fd = reinterpret_cast<const float2*>(feat + (size_t)w * D)[lane];
    float bscale = beta[0] * g_invn[w];    // TEMP == 1
    int beg = g_rowptr[w], end = g_rowptr[w + 1];

    float accx = 0.0f, accy = 0.0f, denom = 0.0f;
    int j = beg;
    for (; j + 1 < end; j += 2) {          // 2-way unroll for ILP
        int s0 = g_esrc[j], s1 = g_esrc[j + 1];
        float2 a0 = reinterpret_cast<const float2*>(feat + (size_t)s0 * D)[lane];
        float2 a1 = reinterpret_cast<const float2*>(feat + (size_t)s1 * D)[lane];
        float p0 = a0.x * fd.x + a0.y * fd.y;
        float p1 = a1.x * fd.x + a1.y * fd.y;
        #pragma unroll
        for (int o = 16; o; o >>= 1) {
            p0 += __shfl_xor_sync(0xffffffffu, p0, o);
            p1 += __shfl_xor_sync(0xffffffffu, p1, o);
        }
        float ex0 = __expf(bscale * g_invn[s0] * p0);
        float ex1 = __expf(bscale * g_invn[s1] * p1);
        denom += ex0 + ex1;
        accx += ex0 * a0.x + ex1 * a1.x;
        accy += ex0 * a0.y + ex1 * a1.y;
    }
    if (j < end) {
        int s0 = g_esrc[j];
        float2 a0 = reinterpret_cast<const float2*>(feat + (size_t)s0 * D)[lane];
        float p0 = a0.x * fd.x + a0.y * fd.y;
        #pragma unroll
        for (int o = 16; o; o >>= 1) p0 += __shfl_xor_sync(0xffffffffu, p0, o);
        float ex0 = __expf(bscale * g_invn[s0] * p0);
        denom += ex0;
        accx += ex0 * a0.x;
        accy += ex0 * a0.y;
    }
    float r = 1.0f / fmaxf(denom, EPSV);
    float2 o2; o2.x = accx * r; o2.y = accy * r;
    reinterpret_cast<float2*>(out + (size_t)w * D)[lane] = o2;
}

// ---------------------------------------------------------------------------
extern "C" void kernel_launch(void* const* d_in, const int* in_sizes, int n_in,
                              void* d_out, int out_size) {
    const float* feat = (const float*)d_in[0];
    const float* beta = (const float*)d_in[1];
    const int*   src  = (const int*)d_in[2];   // JAX default int32 (no x64)
    const int*   dst  = (const int*)d_in[3];
    float*       out  = (float*)d_out;

    int n_nodes = in_sizes[0] / D;
    int n_edges = in_sizes[2];
    if (n_nodes > NN_MAX) n_nodes = NN_MAX;
    if (n_edges > EE_MAX) n_edges = EE_MAX;

    const int T = 256;
    int node_blocks  = (n_nodes + T - 1) / T;
    int edge_blocks  = (n_edges + T - 1) / T;
    int roww_blocks  = (n_nodes + 7) / 8;          // warp-per-row/dst
    int scan_blocks  = (n_nodes + SCAN_B - 1) / SCAN_B;

    k_zero   <<<node_blocks, T>>>(n_nodes);
    k_norm   <<<roww_blocks, T>>>(feat, n_nodes);
    k_hist   <<<edge_blocks, T>>>(dst, n_edges);
    k_scan1  <<<scan_blocks, SCAN_B>>>(n_nodes);
    k_scan2  <<<1, SCAN_B>>>(scan_blocks);
    k_scan3  <<<scan_blocks, SCAN_B>>>(n_nodes, n_edges);
    k_scatter<<<edge_blocks, T>>>(src, dst, n_edges);
    k_agg    <<<roww_blocks, T>>>(feat, beta, out, n_nodes);
}

// round 5
// speedup vs baseline: 3.0739x; 1.7713x over previous
#include <cuda_runtime.h>

#define NN_MAX 100000
#define EE_MAX 1600000
#define D 64
#define EPSV 1e-12f
#define SCAN_B 1024

// Scratch (no allocations allowed)
__device__ float g_invn[NN_MAX];        // 1/max(||feat_row||, eps)
__device__ int   g_hist[NN_MAX];        // in-degree
__device__ int   g_rowptr[NN_MAX + 1];  // CSR row pointers (by dst)
__device__ int   g_cursor[NN_MAX];      // scatter cursors
__device__ int   g_bsums[SCAN_B];       // scan block sums
__device__ int   g_esrc[EE_MAX];        // src ids grouped by dst

// ---------------------------------------------------------------------------
// K1: per-row inverse L2 norm (warp per row) + hist zero (fused)
__global__ void k_norm(const float* __restrict__ feat, int n_nodes) {
    int t    = blockIdx.x * blockDim.x + threadIdx.x;
    int w    = t >> 5;
    int lane = threadIdx.x & 31;
    if (t < n_nodes) g_hist[t] = 0;
    if (w >= n_nodes) return;
    float2 v = reinterpret_cast<const float2*>(feat + (size_t)w * D)[lane];
    float s = v.x * v.x + v.y * v.y;
    #pragma unroll
    for (int o = 16; o; o >>= 1) s += __shfl_xor_sync(0xffffffffu, s, o);
    if (lane == 0) g_invn[w] = 1.0f / fmaxf(sqrtf(s), EPSV);
}

// in-degree histogram
__global__ void k_hist(const int* __restrict__ dst, int n_edges) {
    int i = blockIdx.x * blockDim.x + threadIdx.x;
    if (i < n_edges) atomicAdd(&g_hist[dst[i]], 1);
}

// warp-shuffle inclusive scan helper
__device__ __forceinline__ int warp_iscan(int x, int lane) {
    #pragma unroll
    for (int o = 1; o < 32; o <<= 1) {
        int t = __shfl_up_sync(0xffffffffu, x, o);
        if (lane >= o) x += t;
    }
    return x;
}

// scan stage 1: per-block exclusive scan (warp-scan based) + block totals
__global__ void k_scan1(int n_nodes) {
    __shared__ int wsum[32];
    int i    = blockIdx.x * SCAN_B + threadIdx.x;
    int lane = threadIdx.x & 31;
    int wid  = threadIdx.x >> 5;
    int v = (i < n_nodes) ? g_hist[i] : 0;
    int x = warp_iscan(v, lane);
    if (lane == 31) wsum[wid] = x;
    __syncthreads();
    if (wid == 0) wsum[lane] = warp_iscan(wsum[lane], lane);
    __syncthreads();
    int off = wid ? wsum[wid - 1] : 0;
    if (i < n_nodes) g_rowptr[i] = off + x - v;           // exclusive (partial)
    if (threadIdx.x == SCAN_B - 1) g_bsums[blockIdx.x] = wsum[31];
}

// scan stage 2: exclusive scan of block sums (<=1024 blocks)
__global__ void k_scan2(int n_blocks) {
    __shared__ int wsum[32];
    int lane = threadIdx.x & 31;
    int wid  = threadIdx.x >> 5;
    int v = (threadIdx.x < n_blocks) ? g_bsums[threadIdx.x] : 0;
    int x = warp_iscan(v, lane);
    if (lane == 31) wsum[wid] = x;
    __syncthreads();
    if (wid == 0) wsum[lane] = warp_iscan(wsum[lane], lane);
    __syncthreads();
    int off = wid ? wsum[wid - 1] : 0;
    if (threadIdx.x < n_blocks) g_bsums[threadIdx.x] = off + x - v;
}

// scan stage 3: add block offsets, init cursors, cap row_ptr
__global__ void k_scan3(int n_nodes, int n_edges) {
    int i = blockIdx.x * SCAN_B + threadIdx.x;
    if (i < n_nodes) {
        int r = g_rowptr[i] + g_bsums[blockIdx.x];
        g_rowptr[i] = r;
        g_cursor[i] = r;
    }
    if (i == 0) g_rowptr[n_nodes] = n_edges;
}

// bucket src ids by dst
__global__ void k_scatter(const int* __restrict__ src,
                          const int* __restrict__ dst, int n_edges) {
    int i = blockIdx.x * blockDim.x + threadIdx.x;
    if (i >= n_edges) return;
    int pos = atomicAdd(&g_cursor[dst[i]], 1);
    g_esrc[pos] = src[i];
}

// ---------------------------------------------------------------------------
// fused softmax + aggregation: warp per dst, HALF-WARP per edge.
// lanes 0-15 handle edge 2k, lanes 16-31 handle edge 2k+1; each lane holds
// float4 (16 lanes x 4 = 64 dims). 4-step reduce instead of 5, 2 edges/iter.
__global__ void k_agg(const float* __restrict__ feat,
                      const float* __restrict__ beta,
                      float* __restrict__ out, int n_nodes) {
    int w    = (blockIdx.x * blockDim.x + threadIdx.x) >> 5;
    int lane = threadIdx.x & 31;
    if (w >= n_nodes) return;
    int half = lane >> 4;          // which edge of the pair
    int hl   = lane & 15;          // lane within half (dim group)

    const float4* feat4 = reinterpret_cast<const float4*>(feat);
    float4 fd = feat4[(size_t)w * 16 + hl];
    float bscale = beta[0] * g_invn[w];     // TEMP == 1
    int beg = g_rowptr[w], end = g_rowptr[w + 1];
    int npairs = (end - beg + 1) >> 1;

    float denom = 0.0f;
    float ax = 0.0f, ay = 0.0f, az = 0.0f, aw = 0.0f;

    #pragma unroll 2
    for (int it = 0; it < npairs; it++) {
        int e = beg + 2 * it + half;
        bool valid = (e < end);
        int s = valid ? g_esrc[e] : 0;
        float iv = g_invn[s];
        float4 a = feat4[(size_t)s * 16 + hl];
        float p = a.x * fd.x + a.y * fd.y + a.z * fd.z + a.w * fd.w;
        p += __shfl_xor_sync(0xffffffffu, p, 8);
        p += __shfl_xor_sync(0xffffffffu, p, 4);
        p += __shfl_xor_sync(0xffffffffu, p, 2);
        p += __shfl_xor_sync(0xffffffffu, p, 1);
        float ex = valid ? __expf(bscale * iv * p) : 0.0f;
        denom += ex;
        ax += ex * a.x; ay += ex * a.y; az += ex * a.z; aw += ex * a.w;
    }

    // combine the two halves (lane hl in each half holds the same dims)
    denom += __shfl_xor_sync(0xffffffffu, denom, 16);
    ax += __shfl_xor_sync(0xffffffffu, ax, 16);
    ay += __shfl_xor_sync(0xffffffffu, ay, 16);
    az += __shfl_xor_sync(0xffffffffu, az, 16);
    aw += __shfl_xor_sync(0xffffffffu, aw, 16);

    if (half == 0) {
        float r = 1.0f / fmaxf(denom, EPSV);
        float4 o4; o4.x = ax * r; o4.y = ay * r; o4.z = az * r; o4.w = aw * r;
        reinterpret_cast<float4*>(out)[(size_t)w * 16 + hl] = o4;
    }
}

// ---------------------------------------------------------------------------
extern "C" void kernel_launch(void* const* d_in, const int* in_sizes, int n_in,
                              void* d_out, int out_size) {
    const float* feat = (const float*)d_in[0];
    const float* beta = (const float*)d_in[1];
    const int*   src  = (const int*)d_in[2];   // JAX default int32 (no x64)
    const int*   dst  = (const int*)d_in[3];
    float*       out  = (float*)d_out;

    int n_nodes = in_sizes[0] / D;
    int n_edges = in_sizes[2];
    if (n_nodes > NN_MAX) n_nodes = NN_MAX;
    if (n_edges > EE_MAX) n_edges = EE_MAX;

    const int T = 256;
    int edge_blocks = (n_edges + T - 1) / T;
    int roww_blocks = (n_nodes + 7) / 8;          // warp-per-row/dst
    int scan_blocks = (n_nodes + SCAN_B - 1) / SCAN_B;

    k_norm   <<<roww_blocks, T>>>(feat, n_nodes);
    k_hist   <<<edge_blocks, T>>>(dst, n_edges);
    k_scan1  <<<scan_blocks, SCAN_B>>>(n_nodes);
    k_scan2  <<<1, SCAN_B>>>(scan_blocks);
    k_scan3  <<<scan_blocks, SCAN_B>>>(n_nodes, n_edges);
    k_scatter<<<edge_blocks, T>>>(src, dst, n_edges);
    k_agg    <<<roww_blocks, T>>>(feat, beta, out, n_nodes);
}